// round 3
// baseline (speedup 1.0000x reference)
#include <cuda_runtime.h>
#include <math.h>

#define N_IMG 16
#define HW 10000
#define HDIM 100

typedef unsigned long long ull;

// ---------------- scratch (no allocations allowed) ----------------
__device__ float g_xc[10240000];       // (16,64,100,100)
__device__ float g_A[21233664];        // padded window result buffer
__device__ float g_mix[30720000];      // (16,192,100,100) folded concat

// ---------------- f32x2 packed helpers ----------------
__device__ __forceinline__ ull pk2(float lo, float hi) {
    ull r; asm("mov.b64 %0, {%1,%2};" : "=l"(r) : "f"(lo), "f"(hi)); return r;
}
__device__ __forceinline__ void upk2(ull v, float& lo, float& hi) {
    asm("mov.b64 {%0,%1}, %2;" : "=f"(lo), "=f"(hi) : "l"(v));
}
__device__ __forceinline__ void fma2(ull& d, ull a, ull b) {
    asm("fma.rn.f32x2 %0, %1, %2, %3;" : "=l"(d) : "l"(a), "l"(b), "l"(d));
}

// ---------------- 1x1 conv as tiled SGEMM (f32x2 packed over m) ----------------
// Y[n,m,p] = sum_k W[m,k] * (X0[n,k,p] (+ X1[n,k,p])) + bias[m]
// Block tile: 64 m x 128 p, thread tile 8m x 4p. W in smem transposed (m-consecutive
// pairs read as b64 = natural f32x2 "a" operand); X stored duplicated (x,x).
template<int KDIM, int MOUT, bool ADDX>
__global__ __launch_bounds__(256) void conv1x1_gemm(
    const float* __restrict__ Wm, const float* __restrict__ bias,
    const float* __restrict__ X0, const float* __restrict__ X1,
    float* __restrict__ Y)
{
    extern __shared__ float sm[];
    float* Ws = sm;                  // [KDIM][68] transposed (k-major rows, m inner)
    float* Xs = sm + KDIM * 68;      // dup: [16][264]  (pair (x,x) per p)
    const int tid = threadIdx.x;
    const int tx = tid & 31;         // p group (4 each)
    const int ty = tid >> 5;         // m group (8 each)
    const int p0 = blockIdx.x * 128;
    const int m0 = blockIdx.y * 64;
    const int n  = blockIdx.z;
    const float* Xb0 = X0 + (size_t)n * KDIM * HW;
    const float* Xb1 = X1 ? (X1 + (size_t)n * KDIM * HW) : (const float*)0;

    for (int idx = tid; idx < 64 * KDIM; idx += 256) {
        int mm = idx / KDIM;
        int kc = idx - mm * KDIM;
        Ws[kc * 68 + mm] = Wm[(m0 + mm) * KDIM + kc];
    }

    ull acc[4][4];                   // [m-pair][p]
#pragma unroll
    for (int i = 0; i < 4; i++)
#pragma unroll
        for (int j = 0; j < 4; j++) acc[i][j] = 0ULL;

    for (int k0 = 0; k0 < KDIM; k0 += 16) {
        __syncthreads();
#pragma unroll
        for (int idx = tid; idx < 2048; idx += 256) {
            int kk = idx >> 7;
            int pp = idx & 127;
            int p = p0 + pp;
            float v = 0.f;
            if (p < HW) {
                v = Xb0[(size_t)(k0 + kk) * HW + p];
                if (ADDX) v += Xb1[(size_t)(k0 + kk) * HW + p];
            }
            reinterpret_cast<ull*>(Xs + kk * 264)[pp] = pk2(v, v);
        }
        __syncthreads();
#pragma unroll
        for (int kk = 0; kk < 16; kk++) {
            const ull* wp = reinterpret_cast<const ull*>(Ws + (k0 + kk) * 68 + ty * 8);
            const ull* xp = reinterpret_cast<const ull*>(Xs + kk * 264) + tx * 4;
            ull w01 = wp[0], w23 = wp[1], w45 = wp[2], w67 = wp[3];
            ull x0 = xp[0], x1 = xp[1], x2 = xp[2], x3 = xp[3];
            fma2(acc[0][0], w01, x0); fma2(acc[0][1], w01, x1);
            fma2(acc[0][2], w01, x2); fma2(acc[0][3], w01, x3);
            fma2(acc[1][0], w23, x0); fma2(acc[1][1], w23, x1);
            fma2(acc[1][2], w23, x2); fma2(acc[1][3], w23, x3);
            fma2(acc[2][0], w45, x0); fma2(acc[2][1], w45, x1);
            fma2(acc[2][2], w45, x2); fma2(acc[2][3], w45, x3);
            fma2(acc[3][0], w67, x0); fma2(acc[3][1], w67, x1);
            fma2(acc[3][2], w67, x2); fma2(acc[3][3], w67, x3);
        }
    }

    int p = p0 + tx * 4;
    if (p < HW) {
#pragma unroll
        for (int i = 0; i < 4; i++) {
            float lo[4], hi[4];
#pragma unroll
            for (int j = 0; j < 4; j++) upk2(acc[i][j], lo[j], hi[j]);
            int mA = m0 + ty * 8 + i * 2;
            float bA = bias[mA], bB = bias[mA + 1];
            *reinterpret_cast<float4*>(Y + (size_t)(n * MOUT + mA) * HW + p) =
                make_float4(lo[0] + bA, lo[1] + bA, lo[2] + bA, lo[3] + bA);
            *reinterpret_cast<float4*>(Y + (size_t)(n * MOUT + mA + 1) * HW + p) =
                make_float4(hi[0] + bB, hi[1] + bB, hi[2] + bB, hi[3] + bB);
        }
    }
}

// ---------------- fused: gather + mean + SE + conv1x1(w2)*z + dwconv3x3 ----------------
// One block per patch b; gathers the patch straight from xc (L2-resident),
// computes the SE path inline from the smem-resident patch.
template<int NW, int K, int S, int NT>
__global__ __launch_bounds__(NT) void win_compute(
    const float* __restrict__ xc, const float* __restrict__ w2, const float* __restrict__ b2,
    const float* __restrict__ wpos, const float* __restrict__ bpos,
    const float* __restrict__ wse1, const float* __restrict__ wse2,
    float* __restrict__ A)
{
    constexpr int W2 = NW * NW;
    constexpr int KSQ = K * K;
    constexpr int KSQ4 = (KSQ + 3) & ~3;
    constexpr int M = 64 * KSQ;
    constexpr int M4 = 64 * KSQ4;
    constexpr int NSG = KSQ4 / 4;
    extern __shared__ float smw[];
    float* Us  = smw;                 // 64*KSQ4, [c][sp] padded
    float* w2t = Us + 64 * KSQ4;      // 4096, [c][o]
    float* wps = w2t + 4096;          // 576
    float* zb  = wps + 576;           // 64
    float* b2s = zb + 64;             // 64
    float* bps = b2s + 64;            // 64
    float* mu  = bps + 64;            // 64
    float* my  = mu + 64;             // 64
    float* hb  = my + 64;             // 16
    const int b = blockIdx.x;
    const int tid = threadIdx.x;
    const int nimg = b / W2;
    const int q = b - nimg * W2;
    const size_t gout = (size_t)b * M4;
    const float* xcn = xc + (size_t)nimg * 64 * HW;

    // gather patch: flat f = q*M + c*KSQ + sp within image
    for (int idx = tid; idx < 64 * KSQ4; idx += NT) {
        int c = idx / KSQ4;
        int sp = idx - c * KSQ4;
        float v = 0.f;
        if (sp < KSQ) {
            int f = q * M + c * KSQ + sp;
            int m = f / W2;
            int w = f - m * W2;
            int cin = m / KSQ;
            int rem = m - cin * KSQ;
            int ki = rem / K, kj = rem - ki * K;
            int wi = w / NW, wj = w - wi * NW;
            v = xcn[(cin * HDIM + wi * S + ki) * HDIM + wj * S + kj];
        }
        Us[idx] = v;
    }
    for (int idx = tid; idx < 4096; idx += NT) {
        int c = idx >> 6, o = idx & 63;
        w2t[idx] = w2[o * 64 + c];
    }
    for (int idx = tid; idx < 576; idx += NT) wps[idx] = wpos[idx];
    if (tid < 64) { b2s[tid] = b2[tid]; bps[tid] = bpos[tid]; }
    __syncthreads();

    // per-channel mean: 8 lanes per channel (NT=512 -> 64*8)
    {
        constexpr int LPC = NT / 64;
        int c = tid / LPC;
        int lane = tid - c * LPC;
        const float* row = Us + c * KSQ4;
        float s = 0.f;
        for (int i = lane; i < KSQ; i += LPC) s += row[i];
#pragma unroll
        for (int off = LPC / 2; off; off >>= 1)
            s += __shfl_down_sync(0xffffffffu, s, off, LPC);
        if (lane == 0) mu[c] = s * (1.0f / KSQ);
    }
    __syncthreads();
    // SE: my = w2 @ mu + b2 ; h = relu(wse1 @ my) ; z = sigmoid(wse2 @ h)
    if (tid < 64) {
        float a = b2s[tid];
#pragma unroll 16
        for (int c = 0; c < 64; c++) a += w2t[c * 64 + tid] * mu[c];
        my[tid] = a;
    }
    __syncthreads();
    if (tid < 4) {
        float h = 0.f;
#pragma unroll 16
        for (int o = 0; o < 64; o++) h += wse1[tid * 64 + o] * my[o];
        hb[tid] = fmaxf(h, 0.f);
    }
    __syncthreads();
    if (tid < 64) {
        float za = 0.f;
#pragma unroll
        for (int j = 0; j < 4; j++) za += wse2[tid * 4 + j] * hb[j];
        zb[tid] = 1.f / (1.f + expf(-za));
    }
    __syncthreads();

    const int og = tid >> 5;      // 16 groups of 4 out channels
    const int sg0 = tid & 31;     // spatial float4 group, stride 32
    const float4* Us4  = reinterpret_cast<const float4*>(Us);
    const float4* w2t4 = reinterpret_cast<const float4*>(w2t);

    for (int sg = sg0; sg < NSG; sg += 32) {
        float acc[4][4];
#pragma unroll
        for (int i = 0; i < 4; i++) { acc[i][0] = 0.f; acc[i][1] = 0.f; acc[i][2] = 0.f; acc[i][3] = 0.f; }
#pragma unroll 8
        for (int c = 0; c < 64; c++) {
            float4 u  = Us4[c * NSG + sg];
            float4 wv = w2t4[c * 16 + og];
            acc[0][0] += wv.x * u.x; acc[0][1] += wv.x * u.y; acc[0][2] += wv.x * u.z; acc[0][3] += wv.x * u.w;
            acc[1][0] += wv.y * u.x; acc[1][1] += wv.y * u.y; acc[1][2] += wv.y * u.z; acc[1][3] += wv.y * u.w;
            acc[2][0] += wv.z * u.x; acc[2][1] += wv.z * u.y; acc[2][2] += wv.z * u.z; acc[2][3] += wv.z * u.w;
            acc[3][0] += wv.w * u.x; acc[3][1] += wv.w * u.y; acc[3][2] += wv.w * u.z; acc[3][3] += wv.w * u.w;
        }
        const int sp0 = sg * 4;
#pragma unroll
        for (int oo = 0; oo < 4; oo++) {
            int o = og * 4 + oo;
            const float* urow = Us + o * KSQ4;
            const float* wp = wps + o * 9;
            float zo = zb[o], b2o = b2s[o], bpo = bps[o];
            float outv[4];
#pragma unroll
            for (int ss = 0; ss < 4; ss++) {
                int sp = sp0 + ss;
                float val = 0.f;
                if (sp < KSQ) {
                    int i = sp / K;
                    int j = sp - i * K;
                    float d = bpo;
#pragma unroll
                    for (int di = -1; di <= 1; di++) {
                        int ii = i + di;
                        if (ii >= 0 && ii < K) {
#pragma unroll
                            for (int dj = -1; dj <= 1; dj++) {
                                int jj = j + dj;
                                if (jj >= 0 && jj < K)
                                    d += wp[(di + 1) * 3 + (dj + 1)] * urow[ii * K + jj];
                            }
                        }
                    }
                    val = zo * (acc[oo][ss] + b2o) + d;
                }
                outv[ss] = val;
            }
            *reinterpret_cast<float4*>(A + gout + o * KSQ4 + sp0) =
                make_float4(outv[0], outv[1], outv[2], outv[3]);
        }
    }
}

// ---------------- fold back (gather form, no atomics) ----------------
template<int NW, int K, int S>
__global__ void fold_win(const float* __restrict__ A, float* __restrict__ mix, int woff)
{
    constexpr int W2 = NW * NW, KSQ = K * K, KSQ4 = (KSQ + 3) & ~3;
    constexpr int M = 64 * KSQ, M4 = 64 * KSQ4;
    int e = blockIdx.x * 256 + threadIdx.x;
    if (e >= N_IMG * 64 * HW) return;
    int hw = e % HW;
    int t = e / HW;
    int c = t & 63;
    int n = t >> 6;
    int h = hw / HDIM;
    int w = hw - h * HDIM;
    int wi_hi = min(NW - 1, h / S);
    int wi_lo = (h >= K) ? (h - K) / S + 1 : 0;
    int wj_hi = min(NW - 1, w / S);
    int wj_lo = (w >= K) ? (w - K) / S + 1 : 0;
    const float* An = A + (size_t)n * W2 * M4;
    float sum = 0.f;
    for (int wi = wi_lo; wi <= wi_hi; wi++) {
        int ki = h - wi * S;
        for (int wj = wj_lo; wj <= wj_hi; wj++) {
            int kj = w - wj * S;
            int g = ((c * K + ki) * K + kj) * W2 + wi * NW + wj;
            int q = g / M;
            int mp = g - q * M;
            int o = mp / KSQ;
            int sp = mp - o * KSQ;
            sum += An[(size_t)q * M4 + o * KSQ4 + sp];
        }
    }
    float cnt = (float)((wi_hi - wi_lo + 1) * (wj_hi - wj_lo + 1));
    mix[((size_t)(n * 192 + woff + c)) * HW + hw] = sum / cnt;
}

// ---------------- host-side per-window driver ----------------
template<int NW, int K, int S>
static void run_window(const float* xc, const float* w2, const float* b2, const float* wpos,
                       const float* bpos, const float* wse1, const float* wse2,
                       float* A, float* mix, int woff)
{
    constexpr int W2 = NW * NW, KSQ = K * K, KSQ4 = (KSQ + 3) & ~3;
    constexpr int B = N_IMG * W2;
    constexpr int NT = 512;
    constexpr int smem = (64 * KSQ4 + 4096 + 576 + 336) * 4;
    cudaFuncSetAttribute(win_compute<NW, K, S, NT>, cudaFuncAttributeMaxDynamicSharedMemorySize, smem);
    win_compute<NW, K, S, NT><<<B, NT, smem>>>(xc, w2, b2, wpos, bpos, wse1, wse2, A);
    fold_win<NW, K, S><<<(N_IMG * 64 * HW + 255) / 256, 256>>>(A, mix, woff);
}

extern "C" void kernel_launch(void* const* d_in, const int* in_sizes, int n_in,
                              void* d_out, int out_size)
{
    const float* x    = (const float*)d_in[0];
    const float* w1   = (const float*)d_in[1];
    const float* b1   = (const float*)d_in[2];
    const float* w2   = (const float*)d_in[3];
    const float* b2   = (const float*)d_in[4];
    const float* w3   = (const float*)d_in[5];
    const float* b3   = (const float*)d_in[6];
    const float* wpos = (const float*)d_in[7];
    const float* bpos = (const float*)d_in[8];
    const float* wse1 = (const float*)d_in[9];
    const float* wse2 = (const float*)d_in[10];
    float* out = (float*)d_out;

    float *xc, *A, *mix;
    cudaGetSymbolAddress((void**)&xc, g_xc);
    cudaGetSymbolAddress((void**)&A, g_A);
    cudaGetSymbolAddress((void**)&mix, g_mix);

    constexpr int gemm_smem = (192 * 68 + 16 * 264) * 4;   // 69,120 B
    cudaFuncSetAttribute(conv1x1_gemm<192, 64, false>,
                         cudaFuncAttributeMaxDynamicSharedMemorySize, gemm_smem);
    cudaFuncSetAttribute(conv1x1_gemm<192, 192, true>,
                         cudaFuncAttributeMaxDynamicSharedMemorySize, gemm_smem);

    // 1) xc = w1 @ x + b1
    conv1x1_gemm<192, 64, false><<<dim3(79, 1, 16), 256, gemm_smem>>>(w1, b1, x, (const float*)0, xc);

    // 2) windows: (nw, k, s)
    run_window<4, 25, 25>(xc, w2, b2, wpos, bpos, wse1, wse2, A, mix, 0);
    run_window<8, 16, 12>(xc, w2, b2, wpos, bpos, wse1, wse2, A, mix, 64);
    run_window<12, 12, 8>(xc, w2, b2, wpos, bpos, wse1, wse2, A, mix, 128);

    // 3) out = w3 @ (mix + x) + b3
    conv1x1_gemm<192, 192, true><<<dim3(79, 3, 16), 256, gemm_smem>>>(w3, b3, mix, x, out);
}